// round 2
// baseline (speedup 1.0000x reference)
#include <cuda_runtime.h>
#include <cstdint>

// ParallelEmbedding: out[t, :] = weight[x[t], :] + A[x[t], :] @ B
// NT=16384 tokens, DIM=1024, RANK=256.
// Fused gather + tiled fp32 GEMM using packed fma.rn.f32x2 (FFMA2).

#define NT    16384
#define DIM   1024
#define RANK  256
#define BM    128
#define BN    128
#define BK    32
#define AS_STRIDE (BM + 1)   // 129: odd stride -> conflict-free transposed stores

__device__ __forceinline__ unsigned long long dup_f32(float a) {
    unsigned long long r;
    asm("mov.b64 %0, {%1, %1};" : "=l"(r) : "f"(a));
    return r;
}
__device__ __forceinline__ void fma2(unsigned long long &c,
                                     unsigned long long a,
                                     unsigned long long b) {
    asm("fma.rn.f32x2 %0, %1, %2, %0;" : "+l"(c) : "l"(a), "l"(b));
}
__device__ __forceinline__ void unpack2(unsigned long long v, float &lo, float &hi) {
    asm("mov.b64 {%0, %1}, %2;" : "=f"(lo), "=f"(hi) : "l"(v));
}

__global__ __launch_bounds__(256, 2)
void lora_embed_kernel(const int*   __restrict__ x,
                       const float* __restrict__ W,
                       const float* __restrict__ A,
                       const float* __restrict__ Bmat,
                       float*       __restrict__ out)
{
    __shared__ float As[BK][AS_STRIDE];   // A tile, transposed: As[k][m]
    __shared__ float Bs[BK][BN];          // B tile: Bs[k][n]
    __shared__ int   toks[BM];

    const int tid = threadIdx.x;
    const int tx  = tid & 15;             // 16 cols of threads
    const int ty  = tid >> 4;             // 16 rows of threads
    const int m0  = blockIdx.x * BM;
    const int n0  = blockIdx.y * BN;

    if (tid < BM) toks[tid] = x[m0 + tid];
    __syncthreads();

    // 8x8 fp32 micro-tile per thread, kept packed as 8x4 f32x2 accumulators.
    // Rows: {ty*4+i | i<4} and {64+ty*4+i}; Cols: {tx*4+j} and {64+tx*4+j}.
    unsigned long long acc[8][4];
    #pragma unroll
    for (int i = 0; i < 8; ++i)
        #pragma unroll
        for (int j = 0; j < 4; ++j) acc[i][j] = 0ull;

    for (int k0 = 0; k0 < RANK; k0 += BK) {
        // ---- Load A tile (gathered rows), 128x32, transposed into As ----
        // f4 linear index over 1024 float4s: m = f4/8, k-base = (f4%8)*4.
        // 8 consecutive threads read 128B contiguous of one A row (coalesced);
        // transposed stores hit distinct banks thanks to stride 129.
        #pragma unroll
        for (int it = 0; it < 4; ++it) {
            int f4 = it * 256 + tid;
            int m  = f4 >> 3;
            int kb = (f4 & 7) << 2;
            const float4 v = *reinterpret_cast<const float4*>(
                A + (size_t)toks[m] * RANK + (k0 + kb));
            As[kb + 0][m] = v.x;
            As[kb + 1][m] = v.y;
            As[kb + 2][m] = v.z;
            As[kb + 3][m] = v.w;
        }
        // ---- Load B tile, 32x128, row-major (coalesced 512B per row) ----
        #pragma unroll
        for (int it = 0; it < 4; ++it) {
            int f4 = it * 256 + tid;
            int kk = f4 >> 5;
            int nb = (f4 & 31) << 2;
            *reinterpret_cast<float4*>(&Bs[kk][nb]) =
                *reinterpret_cast<const float4*>(
                    Bmat + (size_t)(k0 + kk) * DIM + (n0 + nb));
        }
        __syncthreads();

        #pragma unroll
        for (int kk = 0; kk < BK; ++kk) {
            // B fragment: two conflict-free LDS.128 (floats 4*tx and 64+4*tx
            // cover banks 0..31 exactly; upper-half warp broadcasts).
            ulonglong2 bb0 = *reinterpret_cast<const ulonglong2*>(&Bs[kk][tx * 4]);
            ulonglong2 bb1 = *reinterpret_cast<const ulonglong2*>(&Bs[kk][64 + tx * 4]);
            unsigned long long b2[4];
            b2[0] = bb0.x; b2[1] = bb0.y; b2[2] = bb1.x; b2[3] = bb1.y;

            #pragma unroll
            for (int i = 0; i < 8; ++i) {
                int r = (i < 4) ? (ty * 4 + i) : (64 + ty * 4 + (i - 4));
                unsigned long long a2 = dup_f32(As[kk][r]);   // broadcast LDS
                fma2(acc[i][0], a2, b2[0]);
                fma2(acc[i][1], a2, b2[1]);
                fma2(acc[i][2], a2, b2[2]);
                fma2(acc[i][3], a2, b2[3]);
            }
        }
        __syncthreads();
    }

    // ---- Epilogue: add gathered weight row, float4 I/O ----
    #pragma unroll
    for (int i = 0; i < 8; ++i) {
        int ml = (i < 4) ? (ty * 4 + i) : (64 + ty * 4 + (i - 4));
        size_t wrow = (size_t)toks[ml] * DIM;
        size_t orow = (size_t)(m0 + ml) * DIM;
        #pragma unroll
        for (int g = 0; g < 2; ++g) {
            int n = n0 + g * 64 + tx * 4;
            float4 wv = *reinterpret_cast<const float4*>(W + wrow + n);
            float lo0, hi0, lo1, hi1;
            unpack2(acc[i][g * 2 + 0], lo0, hi0);
            unpack2(acc[i][g * 2 + 1], lo1, hi1);
            float4 ov = make_float4(lo0 + wv.x, hi0 + wv.y,
                                    lo1 + wv.z, hi1 + wv.w);
            *reinterpret_cast<float4*>(out + orow + n) = ov;
        }
    }
}

extern "C" void kernel_launch(void* const* d_in, const int* in_sizes, int n_in,
                              void* d_out, int out_size) {
    const int*   x = (const int*)  d_in[0];
    const float* W = (const float*)d_in[1];
    const float* A = (const float*)d_in[2];
    const float* B = (const float*)d_in[3];
    float* out = (float*)d_out;

    dim3 grid(NT / BM, DIM / BN);   // 128 x 8 = 1024 CTAs
    lora_embed_kernel<<<grid, 256>>>(x, W, A, B, out);
}

// round 8
// speedup vs baseline: 1.6216x; 1.6216x over previous
#include <cuda_runtime.h>
#include <cuda_bf16.h>
#include <cstdint>

// ParallelEmbedding: out[t,:] = W[x[t],:] + A[x[t],:] @ B
// NT=16384, DIM=1024, RANK=256.
// mma.sync bf16 split-precision GEMM (Ah*Bh + Al*Bh + Ah*Bl), fp32 accum.
// (tcgen05 PTX is sm_103a-gated and this toolchain targets plain sm_103,
//  so we use baseline mma.sync/ldmatrix which still runs on the tensor pipe.)

#define NT    16384
#define DIM   1024
#define RANK  256
#define BM    128          // tokens per CTA
#define BN    128          // dims per CTA
#define KCH   64           // K chunk (4 chunks; 4 k16 steps each)
#define NCHUNK (RANK / KCH)

// SMEM layout (dynamic, byte offsets). Tiles SW128-swizzled, 128B rows.
#define SMEM_TOKS 0            // 128 * 4 B
#define SMEM_AH   1024         // 128 rows * 128 B = 16 KB
#define SMEM_AL   17408
#define SMEM_BH   33792
#define SMEM_BL   50176
#define SMEM_TOTAL 66560

#define SW128(off) ((off) ^ (((off) >> 3) & 0x70))

__device__ __nv_bfloat16 g_BhT[DIM * RANK];   // B^T hi, [DIM][RANK] row-major
__device__ __nv_bfloat16 g_BlT[DIM * RANK];   // B^T lo

__device__ __forceinline__ uint32_t smem_u32(const void* p) {
    uint32_t a;
    asm("{ .reg .u64 t; cvta.to.shared.u64 t, %1; cvt.u32.u64 %0, t; }"
        : "=r"(a) : "l"(p));
    return a;
}
__device__ __forceinline__ void ldsm4(uint32_t* r, uint32_t addr) {
    asm volatile("ldmatrix.sync.aligned.m8n8.x4.shared.b16 {%0,%1,%2,%3}, [%4];"
                 : "=r"(r[0]), "=r"(r[1]), "=r"(r[2]), "=r"(r[3]) : "r"(addr));
}
__device__ __forceinline__ void mma_bf16(float* c, const uint32_t* a,
                                         const uint32_t* b) {
    asm volatile(
        "mma.sync.aligned.m16n8k16.row.col.f32.bf16.bf16.f32 "
        "{%0,%1,%2,%3}, {%4,%5,%6,%7}, {%8,%9}, {%0,%1,%2,%3};"
        : "+f"(c[0]), "+f"(c[1]), "+f"(c[2]), "+f"(c[3])
        : "r"(a[0]), "r"(a[1]), "r"(a[2]), "r"(a[3]), "r"(b[0]), "r"(b[1]));
}
__device__ __forceinline__ uint32_t pack2(__nv_bfloat16 a, __nv_bfloat16 b) {
    __nv_bfloat162 t = __halves2bfloat162(a, b);
    return *reinterpret_cast<uint32_t*>(&t);
}

// ---------------- Prep: B[K][N] fp32 -> B^T hi/lo bf16 [N][K] ----------------
__global__ void prep_B_kernel(const float* __restrict__ B) {
    __shared__ float tile[32][33];
    const int tx = threadIdx.x & 31;
    const int ty = threadIdx.x >> 5;          // 0..7
    const int k0 = blockIdx.x * 32;
    const int n0 = blockIdx.y * 32;
    #pragma unroll
    for (int i = 0; i < 4; ++i)
        tile[ty + 8 * i][tx] = B[(size_t)(k0 + ty + 8 * i) * DIM + n0 + tx];
    __syncthreads();
    #pragma unroll
    for (int i = 0; i < 4; ++i) {
        int nl = ty + 8 * i;
        float v = tile[tx][nl];               // = B[k0+tx][n0+nl]
        __nv_bfloat16 h = __float2bfloat16(v);
        float l = v - __bfloat162float(h);
        size_t o = (size_t)(n0 + nl) * RANK + k0 + tx;
        g_BhT[o] = h;
        g_BlT[o] = __float2bfloat16(l);
    }
}

// ---------------- Main kernel ----------------
__global__ __launch_bounds__(256, 2)
void lora_embed_hmma_kernel(const int*   __restrict__ x,
                            const float* __restrict__ W,
                            const float* __restrict__ A,
                            float*       __restrict__ out)
{
    extern __shared__ char smem[];
    const uint32_t sb  = smem_u32(smem);
    const int tid = threadIdx.x;
    const int wid = tid >> 5;
    const int lid = tid & 31;
    const int wm  = wid >> 1;                 // 0..3 : warp M group (32 rows)
    const int wn  = wid & 1;                  // 0..1 : warp N group (64 cols)
    const int m0  = blockIdx.x * BM;
    const int n0  = blockIdx.y * BN;

    int* toks = reinterpret_cast<int*>(smem + SMEM_TOKS);
    if (tid < BM) toks[tid] = x[m0 + tid];
    __syncthreads();

    // Accumulators: [mfrag][nfrag][reg], 64 fp32 regs.
    float acc[2][8][4];
    #pragma unroll
    for (int i = 0; i < 2; ++i)
        #pragma unroll
        for (int j = 0; j < 8; ++j)
            #pragma unroll
            for (int q = 0; q < 4; ++q) acc[i][j][q] = 0.0f;

    // --- Precompute ldmatrix lane addressing (SW128: kb' = kb ^ (row&7)) ---
    const int t  = lid >> 3;                  // tile index 0..3
    const int r8 = lid & 7;                   // row within 8
    // A tiles (x4): t0=(m0-7,kb0) t1=(m8-15,kb0) t2=(m0-7,kb1) t3=(m8-15,kb1)
    uint32_t a_rowoff[2], a_xr[2];
    #pragma unroll
    for (int mf = 0; mf < 2; ++mf) {
        int row = wm * 32 + mf * 16 + r8 + (t & 1) * 8;
        a_rowoff[mf] = (uint32_t)row * 128;
        a_xr[mf]     = (uint32_t)(row & 7);
    }
    const int a_kbh = t >> 1;
    // B tiles (x4): t0=(nf0,kb0) t1=(nf0,kb1) t2=(nf1,kb0) t3=(nf1,kb1)
    uint32_t b_rowoff[4], b_xr[4];
    #pragma unroll
    for (int nfp = 0; nfp < 4; ++nfp) {
        int nrow = wn * 64 + nfp * 16 + (t >> 1) * 8 + r8;
        b_rowoff[nfp] = (uint32_t)nrow * 128;
        b_xr[nfp]     = (uint32_t)(nrow & 7);
    }
    const int b_kbh = t & 1;

    for (int c = 0; c < NCHUNK; ++c) {
        const int k0 = c * KCH;

        // --- A tile: gather 128 rows x 64 fp32, split -> bf16 hi/lo, SW128 ---
        #pragma unroll
        for (int it = 0; it < 8; ++it) {
            int f4  = it * 256 + tid;          // 0..2047 float4s
            int row = f4 >> 4;                 // 0..127
            int kb  = (f4 & 15) << 2;          // float index 0..60
            const float4 v = *reinterpret_cast<const float4*>(
                A + (size_t)toks[row] * RANK + k0 + kb);
            __nv_bfloat16 h0 = __float2bfloat16(v.x);
            __nv_bfloat16 h1 = __float2bfloat16(v.y);
            __nv_bfloat16 h2 = __float2bfloat16(v.z);
            __nv_bfloat16 h3 = __float2bfloat16(v.w);
            __nv_bfloat16 l0 = __float2bfloat16(v.x - __bfloat162float(h0));
            __nv_bfloat16 l1 = __float2bfloat16(v.y - __bfloat162float(h1));
            __nv_bfloat16 l2 = __float2bfloat16(v.z - __bfloat162float(h2));
            __nv_bfloat16 l3 = __float2bfloat16(v.w - __bfloat162float(h3));
            uint32_t off = SW128((uint32_t)(row * 128 + kb * 2));
            *reinterpret_cast<uint2*>(smem + SMEM_AH + off) =
                make_uint2(pack2(h0, h1), pack2(h2, h3));
            *reinterpret_cast<uint2*>(smem + SMEM_AL + off) =
                make_uint2(pack2(l0, l1), pack2(l2, l3));
        }
        // --- B tiles: 128 rows x 64 bf16 each (hi, lo) from prepped B^T ---
        #pragma unroll
        for (int it = 0; it < 4; ++it) {
            int u = it * 256 + tid;            // 0..1023 uint4s per matrix
            int r = u >> 3;                    // 0..127
            int j = u & 7;
            size_t src = (size_t)(n0 + r) * RANK + k0 + j * 8;
            uint32_t off = SW128((uint32_t)(r * 128 + j * 16));
            *reinterpret_cast<uint4*>(smem + SMEM_BH + off) =
                *reinterpret_cast<const uint4*>(g_BhT + src);
            *reinterpret_cast<uint4*>(smem + SMEM_BL + off) =
                *reinterpret_cast<const uint4*>(g_BlT + src);
        }
        __syncthreads();

        #pragma unroll
        for (int ks = 0; ks < 4; ++ks) {
            // A fragments (hi, lo) for both m-frags
            uint32_t ah[2][4], al[2][4];
            #pragma unroll
            for (int mf = 0; mf < 2; ++mf) {
                uint32_t kb  = (uint32_t)(2 * ks + a_kbh);
                uint32_t off = a_rowoff[mf] + ((kb ^ a_xr[mf]) << 4);
                ldsm4(ah[mf], sb + SMEM_AH + off);
                ldsm4(al[mf], sb + SMEM_AL + off);
            }
            #pragma unroll
            for (int nfp = 0; nfp < 4; ++nfp) {
                uint32_t kb  = (uint32_t)(2 * ks + b_kbh);
                uint32_t off = b_rowoff[nfp] + ((kb ^ b_xr[nfp]) << 4);
                uint32_t bh[4], bl[4];
                ldsm4(bh, sb + SMEM_BH + off);
                ldsm4(bl, sb + SMEM_BL + off);
                #pragma unroll
                for (int h = 0; h < 2; ++h) {        // two n-frags per pair
                    int nf = nfp * 2 + h;
                    #pragma unroll
                    for (int mf = 0; mf < 2; ++mf) {
                        mma_bf16(acc[mf][nf], ah[mf], bh + 2 * h);
                        mma_bf16(acc[mf][nf], al[mf], bh + 2 * h);
                        mma_bf16(acc[mf][nf], ah[mf], bl + 2 * h);
                    }
                }
            }
        }
        __syncthreads();
    }

    // --- Epilogue: fused W gather + store. c-frag: rows l>>2 (+8), cols 2(l&3). ---
    const int cl = (lid & 3) * 2;
    #pragma unroll
    for (int mf = 0; mf < 2; ++mf) {
        int rbase = wm * 32 + mf * 16 + (lid >> 2);
        #pragma unroll
        for (int h = 0; h < 2; ++h) {
            int row = rbase + h * 8;
            const float* wrow = W + (size_t)toks[row] * DIM + n0 + wn * 64;
            float*       orow = out + (size_t)(m0 + row) * DIM + n0 + wn * 64;
            #pragma unroll
            for (int nf = 0; nf < 8; ++nf) {
                int col = nf * 8 + cl;
                float2 wv = *reinterpret_cast<const float2*>(wrow + col);
                float2 ov;
                ov.x = acc[mf][nf][2 * h + 0] + wv.x;
                ov.y = acc[mf][nf][2 * h + 1] + wv.y;
                *reinterpret_cast<float2*>(orow + col) = ov;
            }
        }
    }
}

extern "C" void kernel_launch(void* const* d_in, const int* in_sizes, int n_in,
                              void* d_out, int out_size) {
    const int*   x = (const int*)  d_in[0];
    const float* W = (const float*)d_in[1];
    const float* A = (const float*)d_in[2];
    const float* B = (const float*)d_in[3];
    float* out = (float*)d_out;

    (void)cudaFuncSetAttribute(lora_embed_hmma_kernel,
                               cudaFuncAttributeMaxDynamicSharedMemorySize,
                               SMEM_TOTAL);

    prep_B_kernel<<<dim3(RANK / 32, DIM / 32), 256>>>(B);
    lora_embed_hmma_kernel<<<dim3(NT / BM, DIM / BN), 256, SMEM_TOTAL>>>(x, W, A, out);
}

// round 9
// speedup vs baseline: 2.7988x; 1.7260x over previous
#include <cuda_runtime.h>
#include <cuda_fp16.h>
#include <cstdint>

// ParallelEmbedding: out[t,:] = W[x[t],:] + A[x[t],:] @ B
// NT=16384, DIM=1024, RANK=256.
// Single fp16 mma.sync GEMM (fp32 accum), double-buffered SMEM with
// register-prefetched A gather. rel_err budget ~1e-4 (norm-based) << 1e-3.

#define NT    16384
#define DIM   1024
#define RANK  256
#define BM    128
#define BN    128
#define KCH   64
#define NCHUNK (RANK / KCH)

// SMEM: toks + 2 buffers of (AH 16KB + BH 16KB)
#define SMEM_TOKS 0
#define SMEM_AH   1024
#define SMEM_BH   17408
#define BUF_STRIDE 32768
#define SMEM_TOTAL 66560

#define SW128(off) ((off) ^ (((off) >> 3) & 0x70))

__device__ __half g_BT[DIM * RANK];   // B^T fp16, [DIM][RANK] row-major

__device__ __forceinline__ uint32_t smem_u32(const void* p) {
    uint32_t a;
    asm("{ .reg .u64 t; cvta.to.shared.u64 t, %1; cvt.u32.u64 %0, t; }"
        : "=r"(a) : "l"(p));
    return a;
}
__device__ __forceinline__ void ldsm4(uint32_t* r, uint32_t addr) {
    asm volatile("ldmatrix.sync.aligned.m8n8.x4.shared.b16 {%0,%1,%2,%3}, [%4];"
                 : "=r"(r[0]), "=r"(r[1]), "=r"(r[2]), "=r"(r[3]) : "r"(addr));
}
__device__ __forceinline__ void mma_fp16(float* c, const uint32_t* a,
                                         const uint32_t* b) {
    asm volatile(
        "mma.sync.aligned.m16n8k16.row.col.f32.f16.f16.f32 "
        "{%0,%1,%2,%3}, {%4,%5,%6,%7}, {%8,%9}, {%0,%1,%2,%3};"
        : "+f"(c[0]), "+f"(c[1]), "+f"(c[2]), "+f"(c[3])
        : "r"(a[0]), "r"(a[1]), "r"(a[2]), "r"(a[3]), "r"(b[0]), "r"(b[1]));
}
__device__ __forceinline__ uint32_t packh(float a, float b) {
    __half2 t = __halves2half2(__float2half(a), __float2half(b));
    return *reinterpret_cast<uint32_t*>(&t);
}

// ---------------- Prep: B[K][N] fp32 -> B^T fp16 [N][K] ----------------
__global__ void prep_B_kernel(const float* __restrict__ B) {
    __shared__ float tile[32][33];
    const int tx = threadIdx.x & 31;
    const int ty = threadIdx.x >> 5;
    const int k0 = blockIdx.x * 32;
    const int n0 = blockIdx.y * 32;
    #pragma unroll
    for (int i = 0; i < 4; ++i)
        tile[ty + 8 * i][tx] = B[(size_t)(k0 + ty + 8 * i) * DIM + n0 + tx];
    __syncthreads();
    #pragma unroll
    for (int i = 0; i < 4; ++i) {
        int nl = ty + 8 * i;
        g_BT[(size_t)(n0 + nl) * RANK + k0 + tx] = __float2half(tile[tx][nl]);
    }
}

// ---------------- Main kernel ----------------
__global__ __launch_bounds__(256, 2)
void lora_embed_hmma_kernel(const int*   __restrict__ x,
                            const float* __restrict__ W,
                            const float* __restrict__ A,
                            float*       __restrict__ out)
{
    extern __shared__ char smem[];
    const uint32_t sb  = smem_u32(smem);
    const int tid = threadIdx.x;
    const int wid = tid >> 5;
    const int lid = tid & 31;
    const int wm  = wid >> 1;                 // 0..3 : 32 rows each
    const int wn  = wid & 1;                  // 0..1 : 64 cols each
    const int m0  = blockIdx.x * BM;
    const int n0  = blockIdx.y * BN;

    int* toks = reinterpret_cast<int*>(smem + SMEM_TOKS);
    if (tid < BM) toks[tid] = x[m0 + tid];
    __syncthreads();

    float acc[2][8][4];
    #pragma unroll
    for (int i = 0; i < 2; ++i)
        #pragma unroll
        for (int j = 0; j < 8; ++j)
            #pragma unroll
            for (int q = 0; q < 4; ++q) acc[i][j][q] = 0.0f;

    // --- ldmatrix lane addressing (SW128: kb' = kb ^ (row&7)), as validated R3+ ---
    const int t  = lid >> 3;
    const int r8 = lid & 7;
    uint32_t a_rowoff[2], a_xr[2];
    #pragma unroll
    for (int mf = 0; mf < 2; ++mf) {
        int row = wm * 32 + mf * 16 + r8 + (t & 1) * 8;
        a_rowoff[mf] = (uint32_t)row * 128;
        a_xr[mf]     = (uint32_t)(row & 7);
    }
    const int a_kbh = t >> 1;
    uint32_t b_rowoff[4], b_xr[4];
    #pragma unroll
    for (int nfp = 0; nfp < 4; ++nfp) {
        int nrow = wn * 64 + nfp * 16 + (t >> 1) * 8 + r8;
        b_rowoff[nfp] = (uint32_t)nrow * 128;
        b_xr[nfp]     = (uint32_t)(nrow & 7);
    }
    const int b_kbh = t & 1;

    // --- A gather addressing: per-it fixed row, fixed kb for this thread ---
    const int kbf = (tid & 15) << 2;          // float col 0..60
    const float* aptr[8];
    #pragma unroll
    for (int it = 0; it < 8; ++it) {
        int row = it * 16 + (tid >> 4);
        aptr[it] = A + (size_t)toks[row] * RANK + kbf;
    }
    // A STS target (constant across chunks except buffer)
    const uint32_t a_sts_off =
        SW128((uint32_t)((tid >> 4) * 128 + kbf * 2));  // + it*16*128 handled below

    // --- Prologue: prefetch A chunk 0 ---
    float4 av[8];
    #pragma unroll
    for (int it = 0; it < 8; ++it) av[it] = *reinterpret_cast<const float4*>(aptr[it]);

    for (int c = 0; c < NCHUNK; ++c) {
        const uint32_t bufo = (uint32_t)(c & 1) * BUF_STRIDE;

        // --- STS A (convert fp32 -> fp16), SW128 ---
        #pragma unroll
        for (int it = 0; it < 8; ++it) {
            int row = it * 16 + (tid >> 4);
            uint32_t off = SW128((uint32_t)(row * 128 + kbf * 2));
            *reinterpret_cast<uint2*>(smem + SMEM_AH + bufo + off) =
                make_uint2(packh(av[it].x, av[it].y), packh(av[it].z, av[it].w));
        }
        // --- Load B chunk c (L2-hot prepped fp16) ---
        {
            const int k0 = c * KCH;
            #pragma unroll
            for (int it = 0; it < 4; ++it) {
                int u = it * 256 + tid;
                int r = u >> 3;
                int j = u & 7;
                size_t src = (size_t)(n0 + r) * RANK + k0 + j * 8;
                *reinterpret_cast<uint4*>(
                    smem + SMEM_BH + bufo + SW128((uint32_t)(r * 128 + j * 16))) =
                    *reinterpret_cast<const uint4*>(g_BT + src);
            }
        }
        __syncthreads();

        // --- Prefetch next A chunk (latency overlaps with MMAs below) ---
        if (c + 1 < NCHUNK) {
            #pragma unroll
            for (int it = 0; it < 8; ++it)
                av[it] = *reinterpret_cast<const float4*>(aptr[it] + (c + 1) * KCH);
        }

        // --- Compute chunk c ---
        #pragma unroll
        for (int ks = 0; ks < 4; ++ks) {
            uint32_t ah[2][4];
            #pragma unroll
            for (int mf = 0; mf < 2; ++mf) {
                uint32_t kb  = (uint32_t)(2 * ks + a_kbh);
                uint32_t off = a_rowoff[mf] + ((kb ^ a_xr[mf]) << 4);
                ldsm4(ah[mf], sb + SMEM_AH + bufo + off);
            }
            #pragma unroll
            for (int nfp = 0; nfp < 4; ++nfp) {
                uint32_t kb  = (uint32_t)(2 * ks + b_kbh);
                uint32_t off = b_rowoff[nfp] + ((kb ^ b_xr[nfp]) << 4);
                uint32_t bh[4];
                ldsm4(bh, sb + SMEM_BH + bufo + off);
                #pragma unroll
                for (int h = 0; h < 2; ++h) {
                    int nf = nfp * 2 + h;
                    mma_fp16(acc[0][nf], ah[0], bh + 2 * h);
                    mma_fp16(acc[1][nf], ah[1], bh + 2 * h);
                }
            }
        }
        // No trailing sync needed: next iteration writes the OTHER buffer,
        // and its post-STS sync orders reuse of this one.
    }

    // --- Epilogue: fused W gather + store ---
    const int cl = (lid & 3) * 2;
    #pragma unroll
    for (int mf = 0; mf < 2; ++mf) {
        int rbase = wm * 32 + mf * 16 + (lid >> 2);
        #pragma unroll
        for (int h = 0; h < 2; ++h) {
            int row = rbase + h * 8;
            const float* wrow = W + (size_t)toks[row] * DIM + n0 + wn * 64;
            float*       orow = out + (size_t)(m0 + row) * DIM + n0 + wn * 64;
            #pragma unroll
            for (int nf = 0; nf < 8; ++nf) {
                int col = nf * 8 + cl;
                float2 wv = *reinterpret_cast<const float2*>(wrow + col);
                float2 ov;
                ov.x = acc[mf][nf][2 * h + 0] + wv.x;
                ov.y = acc[mf][nf][2 * h + 1] + wv.y;
                *reinterpret_cast<float2*>(orow + col) = ov;
            }
        }
    }
}

extern "C" void kernel_launch(void* const* d_in, const int* in_sizes, int n_in,
                              void* d_out, int out_size) {
    const int*   x = (const int*)  d_in[0];
    const float* W = (const float*)d_in[1];
    const float* A = (const float*)d_in[2];
    const float* B = (const float*)d_in[3];
    float* out = (float*)d_out;

    (void)cudaFuncSetAttribute(lora_embed_hmma_kernel,
                               cudaFuncAttributeMaxDynamicSharedMemorySize,
                               SMEM_TOTAL);

    prep_B_kernel<<<dim3(RANK / 32, DIM / 32), 256>>>(B);
    lora_embed_hmma_kernel<<<dim3(NT / BM, DIM / BN), 256, SMEM_TOTAL>>>(x, W, A, out);
}